// round 6
// baseline (speedup 1.0000x reference)
#include <cuda_runtime.h>

#define NB   8
#define LIN  32768
#define NC1  51
#define NK1  79
#define NSC  9
#define LP1  8192
#define SMAX 64

// scratch (allocation-free rule: device globals)
__device__ float g_bufA[30081024];   // max 8*51*9*8192
__device__ float g_bufB[7520256];    // max 8*51*9*2048
__device__ float g_wT[1800000];      // transposed gg weights [tap][ci][co]
__device__ float g_psum[408 * SMAX];
__device__ float g_psqs[408 * SMAX];
__device__ float g_scale[408];
__device__ float g_shift[408];

// ---------------------------------------------------------------------------
// packed fp32x2 helpers (FFMA2 — only reachable via PTX)
// ---------------------------------------------------------------------------
__device__ __forceinline__ unsigned long long pack2(float lo, float hi) {
    unsigned long long r;
    asm("mov.b64 %0, {%1, %2};" : "=l"(r) : "f"(lo), "f"(hi));
    return r;
}
__device__ __forceinline__ void fma2(unsigned long long& d,
                                     unsigned long long a, unsigned long long b) {
    asm("fma.rn.f32x2 %0, %1, %2, %0;" : "+l"(d) : "l"(a), "l"(b));
}
__device__ __forceinline__ float2 unpack2(unsigned long long v) {
    float2 f;
    asm("mov.b64 {%0, %1}, %2;" : "=f"(f.x), "=f"(f.y) : "l"(v));
    return f;
}

// ---------------------------------------------------------------------------
// Weight transpose: w[Cout][Cin][NkK] -> wt[tap][ci][co]
// ---------------------------------------------------------------------------
__global__ void wtrans_kernel(const float* __restrict__ w, float* __restrict__ wt,
                              int Cin, int Cout, int NkK)
{
    int n = Cout * Cin * NkK;
    for (int idx = blockIdx.x * blockDim.x + threadIdx.x; idx < n;
         idx += gridDim.x * blockDim.x) {
        int co  = idx % Cout;
        int t   = idx / Cout;
        int ci  = t % Cin;
        int tap = t / Cin;
        wt[idx] = w[(co * Cin + ci) * NkK + tap];
    }
}

// ---------------------------------------------------------------------------
// Lift, 4-raw-l tile (used for d<4: rolling register window)
// ---------------------------------------------------------------------------
__launch_bounds__(416)
__global__ void lift_pool4_kernel(const float* __restrict__ x,
                                  const float* __restrict__ w,
                                  float* __restrict__ out, int s)
{
    extern __shared__ float sm[];
    float* sw = sm;
    float* sx = sm + 79 * 52;
    const int d = 1 << s;
    const float invd = 1.0f / (float)d;
    const int b   = blockIdx.y;
    const int l0  = blockIdx.x * 128;
    const int tid = threadIdx.x;

    for (int t = tid; t < 79 * 52; t += 416) {
        int k = t / 52, co = t - k * 52;
        sw[t] = (co < NC1) ? w[co * NK1 + k] * invd : 0.0f;
    }
    const int nx = 128 + 78 * d + 8;
    const int gb = l0 - 39 * d;
    const float* xb = x + (size_t)b * LIN;
    for (int t = tid; t < nx; t += 416) {
        int g = gb + t;
        sx[t] = (g >= 0 && g < LIN) ? xb[g] : 0.0f;
    }
    __syncthreads();

    const int lg   = tid & 31;
    const int cg   = tid >> 5;
    const int co0  = cg * 4;
    const int base = lg * 4;
    unsigned long long acc2[4][2] = {};

    if (d == 2) {
        float x0 = sx[base], x1 = sx[base+1], x2 = sx[base+2], x3 = sx[base+3];
        for (int k = 0; k < NK1; ++k) {
            float4 wv = *reinterpret_cast<const float4*>(&sw[k * 52 + co0]);
            float wa[4] = {wv.x, wv.y, wv.z, wv.w};
            unsigned long long xp0 = pack2(x0, x1), xp1 = pack2(x2, x3);
            #pragma unroll
            for (int r = 0; r < 4; ++r) {
                unsigned long long wp = pack2(wa[r], wa[r]);
                fma2(acc2[r][0], wp, xp0);
                fma2(acc2[r][1], wp, xp1);
            }
            x0 = x2; x1 = x3;
            x2 = sx[base + 2*k + 4];
            x3 = sx[base + 2*k + 5];
        }
    } else {
        float x0 = sx[base], x1 = sx[base+1], x2 = sx[base+2], x3 = sx[base+3];
        for (int k = 0; k < NK1; ++k) {
            float4 wv = *reinterpret_cast<const float4*>(&sw[k * 52 + co0]);
            float wa[4] = {wv.x, wv.y, wv.z, wv.w};
            unsigned long long xp0 = pack2(x0, x1), xp1 = pack2(x2, x3);
            #pragma unroll
            for (int r = 0; r < 4; ++r) {
                unsigned long long wp = pack2(wa[r], wa[r]);
                fma2(acc2[r][0], wp, xp0);
                fma2(acc2[r][1], wp, xp1);
            }
            x0 = x1; x1 = x2; x2 = x3;
            x3 = sx[base + k + 4];
        }
    }

    const int lp = blockIdx.x * 32 + lg;
    #pragma unroll
    for (int r = 0; r < 4; ++r) {
        int co = co0 + r;
        if (co < NC1) {
            float2 a = unpack2(acc2[r][0]);
            float2 c = unpack2(acc2[r][1]);
            float m = fmaxf(fmaxf(a.x, a.y), fmaxf(c.x, c.y));
            out[(((size_t)b * NC1 + co) * NSC + s) * LP1 + lp] = m;
        }
    }
}

// ---------------------------------------------------------------------------
// Lift, 8-raw-l tile (d>=4, all smem accesses 16B-aligned).
// Per k: 2 LDS.128 (x) + 1 LDS.128 (w) + 4 packs + 16 FMA2 = 32 MACs.
// ---------------------------------------------------------------------------
__launch_bounds__(416)
__global__ void lift_pool8_kernel(const float* __restrict__ x,
                                  const float* __restrict__ w,
                                  float* __restrict__ out, int s)
{
    extern __shared__ float sm[];
    float* sw = sm;
    float* sx = sm + 79 * 52;
    const int d = 1 << s;
    const float invd = 1.0f / (float)d;
    const int b   = blockIdx.y;
    const int l0  = blockIdx.x * 256;
    const int tid = threadIdx.x;

    for (int t = tid; t < 79 * 52; t += 416) {
        int k = t / 52, co = t - k * 52;
        sw[t] = (co < NC1) ? w[co * NK1 + k] * invd : 0.0f;
    }
    const int nx = 256 + 78 * d + 8;
    const int gb = l0 - 39 * d;
    const float* xb = x + (size_t)b * LIN;
    for (int t = tid; t < nx; t += 416) {
        int g = gb + t;
        sx[t] = (g >= 0 && g < LIN) ? xb[g] : 0.0f;
    }
    __syncthreads();

    const int lg   = tid & 31;
    const int cg   = tid >> 5;
    const int co0  = cg * 4;
    const int base = lg * 8;
    unsigned long long acc2[4][4] = {};

    #pragma unroll 2
    for (int k = 0; k < NK1; ++k) {
        const float* xp = &sx[base + k * d];
        ulonglong2 xq0 = *reinterpret_cast<const ulonglong2*>(xp);
        ulonglong2 xq1 = *reinterpret_cast<const ulonglong2*>(xp + 4);
        float4 wv = *reinterpret_cast<const float4*>(&sw[k * 52 + co0]);
        float wa[4] = {wv.x, wv.y, wv.z, wv.w};
        #pragma unroll
        for (int r = 0; r < 4; ++r) {
            unsigned long long wp = pack2(wa[r], wa[r]);
            fma2(acc2[r][0], wp, xq0.x);
            fma2(acc2[r][1], wp, xq0.y);
            fma2(acc2[r][2], wp, xq1.x);
            fma2(acc2[r][3], wp, xq1.y);
        }
    }

    const int lp0 = blockIdx.x * 64 + lg * 2;
    #pragma unroll
    for (int r = 0; r < 4; ++r) {
        int co = co0 + r;
        if (co < NC1) {
            float2 a0 = unpack2(acc2[r][0]);
            float2 a1 = unpack2(acc2[r][1]);
            float2 a2 = unpack2(acc2[r][2]);
            float2 a3 = unpack2(acc2[r][3]);
            float m0 = fmaxf(fmaxf(a0.x, a0.y), fmaxf(a1.x, a1.y));
            float m1 = fmaxf(fmaxf(a2.x, a2.y), fmaxf(a3.x, a3.y));
            size_t ob = (((size_t)b * NC1 + co) * NSC + s) * LP1 + lp0;
            out[ob]     = m0;
            out[ob + 1] = m1;
        }
    }
}

// ---------------------------------------------------------------------------
// GConvGG: tiled GEMM over ci per (i,k) tap, transposed (coalesced) weights,
// 4co x 8l thread tile on fp32x2. fuse != 0: BN+ReLU applied at Bs load.
// ---------------------------------------------------------------------------
template <int COT, int LT>
__launch_bounds__((COT/4)*(LT/8))
__global__ void gg_kernel(const float* __restrict__ in, const float* __restrict__ wt,
                          float* __restrict__ out,
                          int Cin, int Cout, int Hin, int Nk, int L, int fuse)
{
    const int CIC = 16;
    const int TLn = LT / 8;
    const int NT  = (COT/4) * TLn;
    __shared__ __align__(16) float As[CIC][COT];
    __shared__ __align__(16) float Bs[CIC][LT];
    __shared__ float ssc[408], ssh[408];

    const int Hout = Hin - Nk + 1;
    const int s   = blockIdx.z % Hout;
    const int b   = blockIdx.z / Hout;
    const int co0 = blockIdx.y * COT;
    const int l0  = blockIdx.x * LT;
    const int tid = threadIdx.x;
    const int tco = (tid / TLn) * 4;
    const int tl  = (tid % TLn) * 8;

    if (fuse) {
        for (int t = tid; t < Cin; t += NT) {
            ssc[t] = g_scale[t];
            ssh[t] = g_shift[t];
        }
    }

    unsigned long long acc2[4][4] = {};

    for (int i = 0; i < Nk; ++i) {
        const int dd = 1 << (s + i);
        const float invd = 1.0f / (float)dd;
        const float* inb = in + (((size_t)b * Cin) * Hin + (s + i)) * L;
        for (int k = 0; k < 3; ++k) {
            const int off = (k - 1) * dd;
            const float* wtap = wt + (size_t)(i * 3 + k) * Cin * Cout;
            for (int cc = 0; cc < Cin; cc += CIC) {
                __syncthreads();
                for (int t = tid; t < CIC * COT; t += NT) {
                    int row = t / COT, col = t - row * COT;
                    int ci = cc + row, co = co0 + col;
                    float v = 0.0f;
                    if (ci < Cin && co < Cout)
                        v = wtap[ci * Cout + co] * invd;
                    As[row][col] = v;
                }
                for (int t = tid; t < CIC * LT; t += NT) {
                    int row = t / LT, col = t - row * LT;
                    int ci = cc + row;
                    int l  = l0 + off + col;
                    float v = 0.0f;
                    if (ci < Cin && l >= 0 && l < L) {
                        v = inb[(size_t)ci * Hin * L + l];
                        if (fuse) v = fmaxf(fmaf(v, ssc[ci], ssh[ci]), 0.0f);
                    }
                    Bs[row][col] = v;
                }
                __syncthreads();
                #pragma unroll
                for (int ci = 0; ci < CIC; ++ci) {
                    float4 av = *reinterpret_cast<const float4*>(&As[ci][tco]);
                    ulonglong2 bq0 = *reinterpret_cast<const ulonglong2*>(&Bs[ci][tl]);
                    ulonglong2 bq1 = *reinterpret_cast<const ulonglong2*>(&Bs[ci][tl + 4]);
                    float a4[4] = {av.x, av.y, av.z, av.w};
                    #pragma unroll
                    for (int r = 0; r < 4; ++r) {
                        unsigned long long ap = pack2(a4[r], a4[r]);
                        fma2(acc2[r][0], ap, bq0.x);
                        fma2(acc2[r][1], ap, bq0.y);
                        fma2(acc2[r][2], ap, bq1.x);
                        fma2(acc2[r][3], ap, bq1.y);
                    }
                }
            }
        }
    }

    #pragma unroll
    for (int r = 0; r < 4; ++r) {
        int co = co0 + tco + r;
        if (co < Cout) {
            size_t ob = (((size_t)b * Cout + co) * Hout + s) * L + l0 + tl;
            float2 p0 = unpack2(acc2[r][0]);
            float2 p1 = unpack2(acc2[r][1]);
            float2 p2 = unpack2(acc2[r][2]);
            float2 p3 = unpack2(acc2[r][3]);
            *reinterpret_cast<float4*>(&out[ob])     = make_float4(p0.x, p0.y, p1.x, p1.y);
            *reinterpret_cast<float4*>(&out[ob + 4]) = make_float4(p2.x, p2.y, p3.x, p3.y);
        }
    }
}

// ---------------------------------------------------------------------------
// BN stats: per-channel per-split partial sums (no atomics, no zeroing).
// ---------------------------------------------------------------------------
__global__ void stats_kernel(const float* __restrict__ in, int C, int HL)
{
    const int c  = blockIdx.x;
    const int sp = blockIdx.y, S = gridDim.y;
    float s = 0.0f, s2 = 0.0f;
    for (int b = 0; b < NB; ++b) {
        const float* p = in + ((size_t)b * C + c) * HL;
        for (int r = sp * blockDim.x + threadIdx.x; r < HL; r += S * blockDim.x) {
            float v = p[r];
            s += v; s2 = fmaf(v, v, s2);
        }
    }
    __shared__ float rs[256], rq[256];
    rs[threadIdx.x] = s; rq[threadIdx.x] = s2;
    __syncthreads();
    for (int st = 128; st > 0; st >>= 1) {
        if (threadIdx.x < st) {
            rs[threadIdx.x] += rs[threadIdx.x + st];
            rq[threadIdx.x] += rq[threadIdx.x + st];
        }
        __syncthreads();
    }
    if (threadIdx.x == 0) {
        g_psum[c * SMAX + sp] = rs[0];
        g_psqs[c * SMAX + sp] = rq[0];
    }
}

__global__ void finalize_kernel(const float* __restrict__ gamma,
                                const float* __restrict__ beta,
                                int C, int S, double invN)
{
    int c = blockIdx.x * blockDim.x + threadIdx.x;
    if (c >= C) return;
    double s = 0.0, q = 0.0;
    for (int i = 0; i < S; ++i) {
        s += (double)g_psum[c * SMAX + i];
        q += (double)g_psqs[c * SMAX + i];
    }
    double m   = s * invN;
    double var = q * invN - m * m;
    float inv = rsqrtf((float)var + 2e-5f);
    float sc  = gamma[c] * inv;
    g_scale[c] = sc;
    g_shift[c] = beta[c] - (float)m * sc;
}

// ---------------------------------------------------------------------------
// BN apply + ReLU + pool4 (pooled stages only)
// ---------------------------------------------------------------------------
__global__ void bn_pool_kernel(const float* __restrict__ in, float* __restrict__ out,
                               int C, int H, int Lin)
{
    __shared__ float ssc[408], ssh[408];
    for (int c = threadIdx.x; c < C; c += blockDim.x) {
        ssc[c] = g_scale[c];
        ssh[c] = g_shift[c];
    }
    __syncthreads();

    const int Lout = Lin / 4;
    const size_t n = (size_t)NB * C * H * Lout;
    for (size_t i = (size_t)blockIdx.x * blockDim.x + threadIdx.x; i < n;
         i += (size_t)gridDim.x * blockDim.x) {
        int lp = (int)(i % Lout);
        size_t t = i / Lout;
        int h = (int)(t % H); t /= H;
        int c = (int)(t % C);
        size_t ibase = (t * (size_t)H + h) * (size_t)Lin;
        float sc = ssc[c], sh = ssh[c];
        const float* p = in + ibase + 4 * (size_t)lp;
        float y0 = fmaf(p[0], sc, sh);
        float y1 = fmaf(p[1], sc, sh);
        float y2 = fmaf(p[2], sc, sh);
        float y3 = fmaf(p[3], sc, sh);
        float y = fmaxf(fmaxf(y0, y1), fmaxf(y2, y3));
        out[i] = fmaxf(y, 0.0f);
    }
}

// ---------------------------------------------------------------------------
// Final: fused bn10+relu, mean over L=32, 1x1 classifier -> out [8,10]
// ---------------------------------------------------------------------------
__global__ void final_kernel(const float* __restrict__ in,
                             const float* __restrict__ w11,
                             float* __restrict__ out)
{
    __shared__ float mean[NB * 408];
    for (int i = threadIdx.x; i < NB * 408; i += blockDim.x) {
        int c = i % 408;
        float sc = g_scale[c], sh = g_shift[c];
        const float* p = in + (size_t)i * 32;
        float s = 0.0f;
        #pragma unroll
        for (int j = 0; j < 32; ++j)
            s += fmaxf(fmaf(p[j], sc, sh), 0.0f);
        mean[i] = s * (1.0f / 32.0f);
    }
    __syncthreads();
    for (int i = threadIdx.x; i < NB * 10; i += blockDim.x) {
        int b = i / 10, cls = i - b * 10;
        const float* mb = &mean[b * 408];
        const float* wr = &w11[cls * 408];
        float s = 0.0f;
        for (int ci = 0; ci < 408; ++ci) s = fmaf(mb[ci], wr[ci], s);
        out[i] = s;
    }
}

// ---------------------------------------------------------------------------
// Host side
// ---------------------------------------------------------------------------
static void bn_stats(const float* in, const float* g, const float* bta, int C, int H, int Lin)
{
    int HL = H * Lin;
    int S = (NB * HL) / (256 * 16);
    if (S < 1) S = 1; if (S > SMAX) S = SMAX;
    stats_kernel<<<dim3(C, S), 256>>>(in, C, HL);
    double invN = 1.0 / ((double)NB * HL);
    finalize_kernel<<<(C + 255) / 256, 256>>>(g, bta, C, S, invN);
}

static void bn_pool(const float* in, float* out, int C, int H, int Lin)
{
    size_t n = (size_t)NB * C * H * (Lin / 4);
    int grid = (int)((n + 255) / 256);
    if (grid > 8192) grid = 8192;
    bn_pool_kernel<<<grid, 256>>>(in, out, C, H, Lin);
}

static void gg(const float* in, const float* wt, float* out,
               int Cin, int Cout, int Hin, int Nk, int L, int fuse)
{
    int Hout = Hin - Nk + 1;
    int coB = (Cout + 63) / 64;
    if (L >= 128)
        gg_kernel<64, 128><<<dim3(L / 128, coB, NB * Hout), 256>>>(
            in, wt, out, Cin, Cout, Hin, Nk, L, fuse);
    else
        gg_kernel<64, 32><<<dim3(L / 32, coB, NB * Hout), 64>>>(
            in, wt, out, Cin, Cout, Hin, Nk, L, fuse);
}

extern "C" void kernel_launch(void* const* d_in, const int* in_sizes, int n_in,
                              void* d_out, int out_size)
{
    const float* x   = (const float*)d_in[0];
    const float* w1  = (const float*)d_in[1];
    const float* wsrc[9];
    for (int i = 0; i < 9; ++i) wsrc[i] = (const float*)d_in[2 + i];   // w2..w10
    const float* w11 = (const float*)d_in[11];
    const float* gb[20];
    for (int i = 0; i < 20; ++i) gb[i] = (const float*)d_in[12 + i];

    float *A, *B, *WT;
    cudaGetSymbolAddress((void**)&A, g_bufA);
    cudaGetSymbolAddress((void**)&B, g_bufB);
    cudaGetSymbolAddress((void**)&WT, g_wT);

    cudaFuncSetAttribute(lift_pool8_kernel,
                         cudaFuncAttributeMaxDynamicSharedMemorySize, 98304);

    // layer dims: {Cin, Cout, Nk}
    const int ldims[9][3] = {
        {51, 51, 3}, {51, 51, 1}, {51, 102, 3}, {102, 102, 1},
        {102, 204, 3}, {204, 204, 1}, {204, 204, 1}, {204, 408, 3}, {408, 408, 1}
    };
    size_t wofs[10];
    wofs[0] = 0;
    for (int i = 0; i < 9; ++i)
        wofs[i + 1] = wofs[i] + (size_t)ldims[i][0] * ldims[i][1] * ldims[i][2] * 3;
    for (int i = 0; i < 9; ++i) {
        int n = ldims[i][0] * ldims[i][1] * ldims[i][2] * 3;
        int grid = (n + 255) / 256; if (grid > 2048) grid = 2048;
        wtrans_kernel<<<grid, 256>>>(wsrc[i], WT + wofs[i],
                                     ldims[i][0], ldims[i][1], ldims[i][2] * 3);
    }

    // lift + pool4 -> A [8,51,9,8192]
    for (int s = 0; s < NSC; ++s) {
        int d = 1 << s;
        if (d < 4) {
            size_t smem = (size_t)(79 * 52 + 128 + 78 * d + 8) * sizeof(float);
            lift_pool4_kernel<<<dim3(LIN / 128, NB), 416, smem>>>(x, w1, A, s);
        } else {
            size_t smem = (size_t)(79 * 52 + 256 + 78 * d + 8) * sizeof(float);
            lift_pool8_kernel<<<dim3(LIN / 256, NB), 416, smem>>>(x, w1, A, s);
        }
    }

    bn_stats(A, gb[0], gb[1], 51, 9, 8192);
    bn_pool(A, B, 51, 9, 8192);                       // -> B [8,51,9,2048]
    gg(B, WT + wofs[0], A, 51, 51, 9, 3, 2048, 0);    // -> A [8,51,7,2048]
    bn_stats(A, gb[2], gb[3], 51, 7, 2048);
    gg(A, WT + wofs[1], B, 51, 51, 7, 1, 2048, 1);    // -> B [8,51,7,2048]
    bn_stats(B, gb[4], gb[5], 51, 7, 2048);
    bn_pool(B, A, 51, 7, 2048);                       // -> A [8,51,7,512]
    gg(A, WT + wofs[2], B, 51, 102, 7, 3, 512, 0);    // -> B [8,102,5,512]
    bn_stats(B, gb[6], gb[7], 102, 5, 512);
    gg(B, WT + wofs[3], A, 102, 102, 5, 1, 512, 1);   // -> A [8,102,5,512]
    bn_stats(A, gb[8], gb[9], 102, 5, 512);
    bn_pool(A, B, 102, 5, 512);                       // -> B [8,102,5,128]
    gg(B, WT + wofs[4], A, 102, 204, 5, 3, 128, 0);   // -> A [8,204,3,128]
    bn_stats(A, gb[10], gb[11], 204, 3, 128);
    gg(A, WT + wofs[5], B, 204, 204, 3, 1, 128, 1);   // -> B [8,204,3,128]
    bn_stats(B, gb[12], gb[13], 204, 3, 128);
    gg(B, WT + wofs[6], A, 204, 204, 3, 1, 128, 1);   // -> A [8,204,3,128]
    bn_stats(A, gb[14], gb[15], 204, 3, 128);
    bn_pool(A, B, 204, 3, 128);                       // -> B [8,204,3,32]
    gg(B, WT + wofs[7], A, 204, 408, 3, 3, 32, 0);    // -> A [8,408,1,32]
    bn_stats(A, gb[16], gb[17], 408, 1, 32);
    gg(A, WT + wofs[8], B, 408, 408, 1, 1, 32, 1);    // -> B [8,408,1,32]
    bn_stats(B, gb[18], gb[19], 408, 1, 32);

    final_kernel<<<1, 512>>>(B, w11, (float*)d_out);
}

// round 8
// speedup vs baseline: 1.1491x; 1.1491x over previous
#include <cuda_runtime.h>

#define NB   8
#define LIN  32768
#define NC1  51
#define NK1  79
#define NSC  9
#define LP1  8192
#define SMAX 64

// scratch (allocation-free rule: device globals)
__device__ float g_bufA[30081024];   // max 8*51*9*8192
__device__ float g_bufB[7520256];    // max 8*51*9*2048
__device__ float g_wT[1800000];      // transposed gg weights [tap][ci][co]
__device__ float g_psum[408 * SMAX];
__device__ float g_psqs[408 * SMAX];
__device__ float g_scale[408];
__device__ float g_shift[408];

// ---------------------------------------------------------------------------
// packed fp32x2 helpers (FFMA2 — only reachable via PTX)
// ---------------------------------------------------------------------------
__device__ __forceinline__ unsigned long long pack2(float lo, float hi) {
    unsigned long long r;
    asm("mov.b64 %0, {%1, %2};" : "=l"(r) : "f"(lo), "f"(hi));
    return r;
}
__device__ __forceinline__ void fma2(unsigned long long& d,
                                     unsigned long long a, unsigned long long b) {
    asm("fma.rn.f32x2 %0, %1, %2, %0;" : "+l"(d) : "l"(a), "l"(b));
}
__device__ __forceinline__ float2 unpack2(unsigned long long v) {
    float2 f;
    asm("mov.b64 {%0, %1}, %2;" : "=f"(f.x), "=f"(f.y) : "l"(v));
    return f;
}

// ---------------------------------------------------------------------------
// Weight transpose: w[Cout][Cin][NkK] -> wt[tap][ci][co]
// ---------------------------------------------------------------------------
__global__ void wtrans_kernel(const float* __restrict__ w, float* __restrict__ wt,
                              int Cin, int Cout, int NkK)
{
    int n = Cout * Cin * NkK;
    for (int idx = blockIdx.x * blockDim.x + threadIdx.x; idx < n;
         idx += gridDim.x * blockDim.x) {
        int co  = idx % Cout;
        int t   = idx / Cout;
        int ci  = t % Cin;
        int tap = t / Cin;
        wt[idx] = w[(co * Cin + ci) * NkK + tap];
    }
}

// ---------------------------------------------------------------------------
// Lift (K=79, dilation 2^s, /2^s) fused with pool4.
// 224 threads = 7 warps; warp = 8 output channels (as 4 packed co-pairs),
// lane = 4 raw l (one pooled output). Per k: 2 broadcast LDS (w pairs),
// 1 LDS.128 (x, conflict-free), 4 dup packs, 16 FMA2 = 32 MACs / 23 slots.
// ---------------------------------------------------------------------------
__launch_bounds__(224)
__global__ void lift_pool_kernel(const float* __restrict__ x,
                                 const float* __restrict__ w,
                                 float* __restrict__ out, int s)
{
    extern __shared__ float sm[];
    float* sw = sm;             // [79][64] pre-scaled weights (co padded)
    float* sx = sm + 79 * 64;   // input window
    const int d = 1 << s;
    const float invd = 1.0f / (float)d;
    const int b   = blockIdx.y;
    const int l0  = blockIdx.x * 128;
    const int tid = threadIdx.x;

    for (int t = tid; t < 79 * 64; t += 224) {
        int k = t >> 6, co = t & 63;
        sw[t] = (co < NC1) ? w[co * NK1 + k] * invd : 0.0f;
    }
    const int nx = 128 + 78 * d + 8;
    const int gb = l0 - 39 * d;
    const float* xb = x + (size_t)b * LIN;
    for (int t = tid; t < nx; t += 224) {
        int g = gb + t;
        sx[t] = (g >= 0 && g < LIN) ? xb[g] : 0.0f;
    }
    __syncthreads();

    const int lg   = tid & 31;
    const int wp   = tid >> 5;     // 0..6
    const int co0  = wp * 8;
    const int base = lg * 4;
    unsigned long long acc2[4][4] = {};   // [co-pair][l]

    if (d >= 4) {
        #pragma unroll 2
        for (int k = 0; k < NK1; ++k) {
            float4 xv = *reinterpret_cast<const float4*>(&sx[base + k * d]);
            ulonglong2 w01 = *reinterpret_cast<const ulonglong2*>(&sw[k * 64 + co0]);
            ulonglong2 w23 = *reinterpret_cast<const ulonglong2*>(&sw[k * 64 + co0 + 4]);
            unsigned long long bd0 = pack2(xv.x, xv.x);
            unsigned long long bd1 = pack2(xv.y, xv.y);
            unsigned long long bd2 = pack2(xv.z, xv.z);
            unsigned long long bd3 = pack2(xv.w, xv.w);
            fma2(acc2[0][0], w01.x, bd0); fma2(acc2[0][1], w01.x, bd1);
            fma2(acc2[0][2], w01.x, bd2); fma2(acc2[0][3], w01.x, bd3);
            fma2(acc2[1][0], w01.y, bd0); fma2(acc2[1][1], w01.y, bd1);
            fma2(acc2[1][2], w01.y, bd2); fma2(acc2[1][3], w01.y, bd3);
            fma2(acc2[2][0], w23.x, bd0); fma2(acc2[2][1], w23.x, bd1);
            fma2(acc2[2][2], w23.x, bd2); fma2(acc2[2][3], w23.x, bd3);
            fma2(acc2[3][0], w23.y, bd0); fma2(acc2[3][1], w23.y, bd1);
            fma2(acc2[3][2], w23.y, bd2); fma2(acc2[3][3], w23.y, bd3);
        }
    } else if (d == 2) {
        float x0 = sx[base], x1 = sx[base+1], x2 = sx[base+2], x3 = sx[base+3];
        for (int k = 0; k < NK1; ++k) {
            ulonglong2 w01 = *reinterpret_cast<const ulonglong2*>(&sw[k * 64 + co0]);
            ulonglong2 w23 = *reinterpret_cast<const ulonglong2*>(&sw[k * 64 + co0 + 4]);
            unsigned long long bd0 = pack2(x0, x0);
            unsigned long long bd1 = pack2(x1, x1);
            unsigned long long bd2 = pack2(x2, x2);
            unsigned long long bd3 = pack2(x3, x3);
            fma2(acc2[0][0], w01.x, bd0); fma2(acc2[0][1], w01.x, bd1);
            fma2(acc2[0][2], w01.x, bd2); fma2(acc2[0][3], w01.x, bd3);
            fma2(acc2[1][0], w01.y, bd0); fma2(acc2[1][1], w01.y, bd1);
            fma2(acc2[1][2], w01.y, bd2); fma2(acc2[1][3], w01.y, bd3);
            fma2(acc2[2][0], w23.x, bd0); fma2(acc2[2][1], w23.x, bd1);
            fma2(acc2[2][2], w23.x, bd2); fma2(acc2[2][3], w23.x, bd3);
            fma2(acc2[3][0], w23.y, bd0); fma2(acc2[3][1], w23.y, bd1);
            fma2(acc2[3][2], w23.y, bd2); fma2(acc2[3][3], w23.y, bd3);
            x0 = x2; x1 = x3;
            x2 = sx[base + 2*k + 4];
            x3 = sx[base + 2*k + 5];
        }
    } else {
        float x0 = sx[base], x1 = sx[base+1], x2 = sx[base+2], x3 = sx[base+3];
        for (int k = 0; k < NK1; ++k) {
            ulonglong2 w01 = *reinterpret_cast<const ulonglong2*>(&sw[k * 64 + co0]);
            ulonglong2 w23 = *reinterpret_cast<const ulonglong2*>(&sw[k * 64 + co0 + 4]);
            unsigned long long bd0 = pack2(x0, x0);
            unsigned long long bd1 = pack2(x1, x1);
            unsigned long long bd2 = pack2(x2, x2);
            unsigned long long bd3 = pack2(x3, x3);
            fma2(acc2[0][0], w01.x, bd0); fma2(acc2[0][1], w01.x, bd1);
            fma2(acc2[0][2], w01.x, bd2); fma2(acc2[0][3], w01.x, bd3);
            fma2(acc2[1][0], w01.y, bd0); fma2(acc2[1][1], w01.y, bd1);
            fma2(acc2[1][2], w01.y, bd2); fma2(acc2[1][3], w01.y, bd3);
            fma2(acc2[2][0], w23.x, bd0); fma2(acc2[2][1], w23.x, bd1);
            fma2(acc2[2][2], w23.x, bd2); fma2(acc2[2][3], w23.x, bd3);
            fma2(acc2[3][0], w23.y, bd0); fma2(acc2[3][1], w23.y, bd1);
            fma2(acc2[3][2], w23.y, bd2); fma2(acc2[3][3], w23.y, bd3);
            x0 = x1; x1 = x2; x2 = x3;
            x3 = sx[base + k + 4];
        }
    }

    const int lp = blockIdx.x * 32 + lg;
    #pragma unroll
    for (int p = 0; p < 4; ++p) {
        float2 v0 = unpack2(acc2[p][0]);
        float2 v1 = unpack2(acc2[p][1]);
        float2 v2 = unpack2(acc2[p][2]);
        float2 v3 = unpack2(acc2[p][3]);
        int co_e = co0 + 2 * p, co_o = co_e + 1;
        if (co_e < NC1) {
            float m = fmaxf(fmaxf(v0.x, v1.x), fmaxf(v2.x, v3.x));
            out[(((size_t)b * NC1 + co_e) * NSC + s) * LP1 + lp] = m;
        }
        if (co_o < NC1) {
            float m = fmaxf(fmaxf(v0.y, v1.y), fmaxf(v2.y, v3.y));
            out[(((size_t)b * NC1 + co_o) * NSC + s) * LP1 + lp] = m;
        }
    }
}

// ---------------------------------------------------------------------------
// GConvGG: tiled GEMM over ci per (i,k) tap, coalesced transposed weights.
// Thread tile 8co (4 packed pairs) x 4l. fuse != 0: BN+ReLU at Bs load.
// ---------------------------------------------------------------------------
template <int COT, int LT>
__launch_bounds__((COT/8)*(LT/4))
__global__ void gg_kernel(const float* __restrict__ in, const float* __restrict__ wt,
                          float* __restrict__ out,
                          int Cin, int Cout, int Hin, int Nk, int L, int fuse)
{
    const int CIC = 16;
    const int TLn = LT / 4;
    const int NT  = (COT/8) * TLn;
    __shared__ __align__(16) float As[CIC][COT];
    __shared__ __align__(16) float Bs[CIC][LT];
    __shared__ float ssc[408], ssh[408];

    const int Hout = Hin - Nk + 1;
    const int s   = blockIdx.z % Hout;
    const int b   = blockIdx.z / Hout;
    const int co0 = blockIdx.y * COT;
    const int l0  = blockIdx.x * LT;
    const int tid = threadIdx.x;
    const int tco = (tid / TLn) * 8;
    const int tl  = (tid % TLn) * 4;

    if (fuse) {
        for (int t = tid; t < Cin; t += NT) {
            ssc[t] = g_scale[t];
            ssh[t] = g_shift[t];
        }
    }

    unsigned long long acc2[4][4] = {};   // [co-pair][l]

    for (int i = 0; i < Nk; ++i) {
        const int dd = 1 << (s + i);
        const float invd = 1.0f / (float)dd;
        const float* inb = in + (((size_t)b * Cin) * Hin + (s + i)) * L;
        for (int k = 0; k < 3; ++k) {
            const int off = (k - 1) * dd;
            const float* wtap = wt + (size_t)(i * 3 + k) * Cin * Cout;
            for (int cc = 0; cc < Cin; cc += CIC) {
                __syncthreads();
                for (int t = tid; t < CIC * COT; t += NT) {
                    int row = t / COT, col = t - row * COT;
                    int ci = cc + row, co = co0 + col;
                    float v = 0.0f;
                    if (ci < Cin && co < Cout)
                        v = wtap[ci * Cout + co] * invd;
                    As[row][col] = v;
                }
                for (int t = tid; t < CIC * LT; t += NT) {
                    int row = t / LT, col = t - row * LT;
                    int ci = cc + row;
                    int l  = l0 + off + col;
                    float v = 0.0f;
                    if (ci < Cin && l >= 0 && l < L) {
                        v = inb[(size_t)ci * Hin * L + l];
                        if (fuse) v = fmaxf(fmaf(v, ssc[ci], ssh[ci]), 0.0f);
                    }
                    Bs[row][col] = v;
                }
                __syncthreads();
                #pragma unroll
                for (int ci = 0; ci < CIC; ++ci) {
                    ulonglong2 a01 = *reinterpret_cast<const ulonglong2*>(&As[ci][tco]);
                    ulonglong2 a23 = *reinterpret_cast<const ulonglong2*>(&As[ci][tco + 4]);
                    float4 bv = *reinterpret_cast<const float4*>(&Bs[ci][tl]);
                    unsigned long long bd0 = pack2(bv.x, bv.x);
                    unsigned long long bd1 = pack2(bv.y, bv.y);
                    unsigned long long bd2 = pack2(bv.z, bv.z);
                    unsigned long long bd3 = pack2(bv.w, bv.w);
                    fma2(acc2[0][0], a01.x, bd0); fma2(acc2[0][1], a01.x, bd1);
                    fma2(acc2[0][2], a01.x, bd2); fma2(acc2[0][3], a01.x, bd3);
                    fma2(acc2[1][0], a01.y, bd0); fma2(acc2[1][1], a01.y, bd1);
                    fma2(acc2[1][2], a01.y, bd2); fma2(acc2[1][3], a01.y, bd3);
                    fma2(acc2[2][0], a23.x, bd0); fma2(acc2[2][1], a23.x, bd1);
                    fma2(acc2[2][2], a23.x, bd2); fma2(acc2[2][3], a23.x, bd3);
                    fma2(acc2[3][0], a23.y, bd0); fma2(acc2[3][1], a23.y, bd1);
                    fma2(acc2[3][2], a23.y, bd2); fma2(acc2[3][3], a23.y, bd3);
                }
            }
        }
    }

    #pragma unroll
    for (int p = 0; p < 4; ++p) {
        float2 v0 = unpack2(acc2[p][0]);
        float2 v1 = unpack2(acc2[p][1]);
        float2 v2 = unpack2(acc2[p][2]);
        float2 v3 = unpack2(acc2[p][3]);
        int co_e = co0 + tco + 2 * p, co_o = co_e + 1;
        if (co_e < Cout) {
            size_t ob = (((size_t)b * Cout + co_e) * Hout + s) * L + l0 + tl;
            *reinterpret_cast<float4*>(&out[ob]) = make_float4(v0.x, v1.x, v2.x, v3.x);
        }
        if (co_o < Cout) {
            size_t ob = (((size_t)b * Cout + co_o) * Hout + s) * L + l0 + tl;
            *reinterpret_cast<float4*>(&out[ob]) = make_float4(v0.y, v1.y, v2.y, v3.y);
        }
    }
}

// ---------------------------------------------------------------------------
// BN stats: per-channel per-split partial sums (no atomics, no zeroing).
// ---------------------------------------------------------------------------
__global__ void stats_kernel(const float* __restrict__ in, int C, int HL)
{
    const int c  = blockIdx.x;
    const int sp = blockIdx.y, S = gridDim.y;
    float s = 0.0f, s2 = 0.0f;
    for (int b = 0; b < NB; ++b) {
        const float* p = in + ((size_t)b * C + c) * HL;
        for (int r = sp * blockDim.x + threadIdx.x; r < HL; r += S * blockDim.x) {
            float v = p[r];
            s += v; s2 = fmaf(v, v, s2);
        }
    }
    __shared__ float rs[256], rq[256];
    rs[threadIdx.x] = s; rq[threadIdx.x] = s2;
    __syncthreads();
    for (int st = 128; st > 0; st >>= 1) {
        if (threadIdx.x < st) {
            rs[threadIdx.x] += rs[threadIdx.x + st];
            rq[threadIdx.x] += rq[threadIdx.x + st];
        }
        __syncthreads();
    }
    if (threadIdx.x == 0) {
        g_psum[c * SMAX + sp] = rs[0];
        g_psqs[c * SMAX + sp] = rq[0];
    }
}

__global__ void finalize_kernel(const float* __restrict__ gamma,
                                const float* __restrict__ beta,
                                int C, int S, double invN)
{
    int c = blockIdx.x * blockDim.x + threadIdx.x;
    if (c >= C) return;
    double s = 0.0, q = 0.0;
    for (int i = 0; i < S; ++i) {
        s += (double)g_psum[c * SMAX + i];
        q += (double)g_psqs[c * SMAX + i];
    }
    double m   = s * invN;
    double var = q * invN - m * m;
    float inv = rsqrtf((float)var + 2e-5f);
    float sc  = gamma[c] * inv;
    g_scale[c] = sc;
    g_shift[c] = beta[c] - (float)m * sc;
}

// ---------------------------------------------------------------------------
// BN apply + ReLU + pool4 (pooled stages only)
// ---------------------------------------------------------------------------
__global__ void bn_pool_kernel(const float* __restrict__ in, float* __restrict__ out,
                               int C, int H, int Lin)
{
    __shared__ float ssc[408], ssh[408];
    for (int c = threadIdx.x; c < C; c += blockDim.x) {
        ssc[c] = g_scale[c];
        ssh[c] = g_shift[c];
    }
    __syncthreads();

    const int Lout = Lin / 4;
    const size_t n = (size_t)NB * C * H * Lout;
    for (size_t i = (size_t)blockIdx.x * blockDim.x + threadIdx.x; i < n;
         i += (size_t)gridDim.x * blockDim.x) {
        int lp = (int)(i % Lout);
        size_t t = i / Lout;
        int h = (int)(t % H); t /= H;
        int c = (int)(t % C);
        size_t ibase = (t * (size_t)H + h) * (size_t)Lin;
        float sc = ssc[c], sh = ssh[c];
        const float* p = in + ibase + 4 * (size_t)lp;
        float y0 = fmaf(p[0], sc, sh);
        float y1 = fmaf(p[1], sc, sh);
        float y2 = fmaf(p[2], sc, sh);
        float y3 = fmaf(p[3], sc, sh);
        float y = fmaxf(fmaxf(y0, y1), fmaxf(y2, y3));
        out[i] = fmaxf(y, 0.0f);
    }
}

// ---------------------------------------------------------------------------
// Final: fused bn10+relu, mean over L=32, 1x1 classifier -> out [8,10]
// ---------------------------------------------------------------------------
__global__ void final_kernel(const float* __restrict__ in,
                             const float* __restrict__ w11,
                             float* __restrict__ out)
{
    __shared__ float mean[NB * 408];
    for (int i = threadIdx.x; i < NB * 408; i += blockDim.x) {
        int c = i % 408;
        float sc = g_scale[c], sh = g_shift[c];
        const float* p = in + (size_t)i * 32;
        float s = 0.0f;
        #pragma unroll
        for (int j = 0; j < 32; ++j)
            s += fmaxf(fmaf(p[j], sc, sh), 0.0f);
        mean[i] = s * (1.0f / 32.0f);
    }
    __syncthreads();
    for (int i = threadIdx.x; i < NB * 10; i += blockDim.x) {
        int b = i / 10, cls = i - b * 10;
        const float* mb = &mean[b * 408];
        const float* wr = &w11[cls * 408];
        float s = 0.0f;
        for (int ci = 0; ci < 408; ++ci) s = fmaf(mb[ci], wr[ci], s);
        out[i] = s;
    }
}

// ---------------------------------------------------------------------------
// Host side
// ---------------------------------------------------------------------------
static void bn_stats(const float* in, const float* g, const float* bta, int C, int H, int Lin)
{
    int HL = H * Lin;
    int S = (NB * HL) / (256 * 16);
    if (S < 1) S = 1; if (S > SMAX) S = SMAX;
    stats_kernel<<<dim3(C, S), 256>>>(in, C, HL);
    double invN = 1.0 / ((double)NB * HL);
    finalize_kernel<<<(C + 255) / 256, 256>>>(g, bta, C, S, invN);
}

static void bn_pool(const float* in, float* out, int C, int H, int Lin)
{
    size_t n = (size_t)NB * C * H * (Lin / 4);
    int grid = (int)((n + 255) / 256);
    if (grid > 8192) grid = 8192;
    bn_pool_kernel<<<grid, 256>>>(in, out, C, H, Lin);
}

static void gg(const float* in, const float* wt, float* out,
               int Cin, int Cout, int Hin, int Nk, int L, int fuse)
{
    int Hout = Hin - Nk + 1;
    if (L >= 256)
        gg_kernel<64, 128><<<dim3(L / 128, (Cout + 63) / 64, NB * Hout), 256>>>(
            in, wt, out, Cin, Cout, Hin, Nk, L, fuse);
    else if (L == 128)
        gg_kernel<64, 64><<<dim3(2, (Cout + 63) / 64, NB * Hout), 128>>>(
            in, wt, out, Cin, Cout, Hin, Nk, L, fuse);
    else
        gg_kernel<128, 32><<<dim3(1, (Cout + 127) / 128, NB * Hout), 128>>>(
            in, wt, out, Cin, Cout, Hin, Nk, L, fuse);
}

extern "C" void kernel_launch(void* const* d_in, const int* in_sizes, int n_in,
                              void* d_out, int out_size)
{
    const float* x   = (const float*)d_in[0];
    const float* w1  = (const float*)d_in[1];
    const float* wsrc[9];
    for (int i = 0; i < 9; ++i) wsrc[i] = (const float*)d_in[2 + i];   // w2..w10
    const float* w11 = (const float*)d_in[11];
    const float* gb[20];
    for (int i = 0; i < 20; ++i) gb[i] = (const float*)d_in[12 + i];

    float *A, *B, *WT;
    cudaGetSymbolAddress((void**)&A, g_bufA);
    cudaGetSymbolAddress((void**)&B, g_bufB);
    cudaGetSymbolAddress((void**)&WT, g_wT);

    cudaFuncSetAttribute(lift_pool_kernel,
                         cudaFuncAttributeMaxDynamicSharedMemorySize, 102400);

    // layer dims: {Cin, Cout, Nk}
    const int ldims[9][3] = {
        {51, 51, 3}, {51, 51, 1}, {51, 102, 3}, {102, 102, 1},
        {102, 204, 3}, {204, 204, 1}, {204, 204, 1}, {204, 408, 3}, {408, 408, 1}
    };
    size_t wofs[10];
    wofs[0] = 0;
    for (int i = 0; i < 9; ++i)
        wofs[i + 1] = wofs[i] + (size_t)ldims[i][0] * ldims[i][1] * ldims[i][2] * 3;
    for (int i = 0; i < 9; ++i) {
        int n = ldims[i][0] * ldims[i][1] * ldims[i][2] * 3;
        int grid = (n + 255) / 256; if (grid > 2048) grid = 2048;
        wtrans_kernel<<<grid, 256>>>(wsrc[i], WT + wofs[i],
                                     ldims[i][0], ldims[i][1], ldims[i][2] * 3);
    }

    // lift + pool4 -> A [8,51,9,8192]
    for (int s = 0; s < NSC; ++s) {
        int d = 1 << s;
        size_t smem = (size_t)(79 * 64 + 128 + 78 * d + 8) * sizeof(float);
        lift_pool_kernel<<<dim3(LIN / 128, NB), 224, smem>>>(x, w1, A, s);
    }

    bn_stats(A, gb[0], gb[1], 51, 9, 8192);
    bn_pool(A, B, 51, 9, 8192);                       // -> B [8,51,9,2048]
    gg(B, WT + wofs[0], A, 51, 51, 9, 3, 2048, 0);    // -> A [8,51,7,2048]
    bn_stats(A, gb[2], gb[3], 51, 7, 2048);
    gg(A, WT + wofs[1], B, 51, 51, 7, 1, 2048, 1);    // -> B [8,51,7,2048]
    bn_stats(B, gb[4], gb[5], 51, 7, 2048);
    bn_pool(B, A, 51, 7, 2048);                       // -> A [8,51,7,512]
    gg(A, WT + wofs[2], B, 51, 102, 7, 3, 512, 0);    // -> B [8,102,5,512]
    bn_stats(B, gb[6], gb[7], 102, 5, 512);
    gg(B, WT + wofs[3], A, 102, 102, 5, 1, 512, 1);   // -> A [8,102,5,512]
    bn_stats(A, gb[8], gb[9], 102, 5, 512);
    bn_pool(A, B, 102, 5, 512);                       // -> B [8,102,5,128]
    gg(B, WT + wofs[4], A, 102, 204, 5, 3, 128, 0);   // -> A [8,204,3,128]
    bn_stats(A, gb[10], gb[11], 204, 3, 128);
    gg(A, WT + wofs[5], B, 204, 204, 3, 1, 128, 1);   // -> B [8,204,3,128]
    bn_stats(B, gb[12], gb[13], 204, 3, 128);
    gg(B, WT + wofs[6], A, 204, 204, 3, 1, 128, 1);   // -> A [8,204,3,128]
    bn_stats(A, gb[14], gb[15], 204, 3, 128);
    bn_pool(A, B, 204, 3, 128);                       // -> B [8,204,3,32]
    gg(B, WT + wofs[7], A, 204, 408, 3, 3, 32, 0);    // -> A [8,408,1,32]
    bn_stats(A, gb[16], gb[17], 408, 1, 32);
    gg(A, WT + wofs[8], B, 408, 408, 1, 1, 32, 1);    // -> B [8,408,1,32]
    bn_stats(B, gb[18], gb[19], 408, 1, 32);

    final_kernel<<<1, 512>>>(B, w11, (float*)d_out);
}

// round 9
// speedup vs baseline: 1.2305x; 1.0709x over previous
#include <cuda_runtime.h>

#define NB   8
#define LIN  32768
#define NC1  51
#define NK1  79
#define NSC  9
#define LP1  8192
#define SMAX 64

// scratch (allocation-free rule: device globals)
__device__ float g_bufA[30081024];   // max 8*51*9*8192
__device__ float g_bufB[7520256];    // max 8*51*9*2048
__device__ float g_wT[1800000];      // transposed gg weights [layer][tap][ci][co]
__device__ float g_psum[408 * SMAX];
__device__ float g_psqs[408 * SMAX];
__device__ float g_scale[408];
__device__ float g_shift[408];

// layer dims for the 9 gg layers: {Cin, Cout, Nk*3}
#define GG_NLAYERS 9
__device__ __constant__ int c_CIN[GG_NLAYERS]  = {51, 51, 51, 102, 102, 204, 204, 204, 408};
__device__ __constant__ int c_COUT[GG_NLAYERS] = {51, 51, 102, 102, 204, 204, 204, 408, 408};
__device__ __constant__ int c_NKK[GG_NLAYERS]  = {9, 3, 9, 3, 9, 3, 3, 9, 3};

// ---------------------------------------------------------------------------
// packed fp32x2 helpers (FFMA2 — only reachable via PTX)
// ---------------------------------------------------------------------------
__device__ __forceinline__ unsigned long long pack2(float lo, float hi) {
    unsigned long long r;
    asm("mov.b64 %0, {%1, %2};" : "=l"(r) : "f"(lo), "f"(hi));
    return r;
}
__device__ __forceinline__ void fma2(unsigned long long& d,
                                     unsigned long long a, unsigned long long b) {
    asm("fma.rn.f32x2 %0, %1, %2, %0;" : "+l"(d) : "l"(a), "l"(b));
}
__device__ __forceinline__ float2 unpack2(unsigned long long v) {
    float2 f;
    asm("mov.b64 {%0, %1}, %2;" : "=f"(f.x), "=f"(f.y) : "l"(v));
    return f;
}

// ---------------------------------------------------------------------------
// One-shot weight transpose for ALL gg layers:
// w[Cout][Cin][NkK] -> wt[tap][ci][co] per layer, concatenated.
// ---------------------------------------------------------------------------
__global__ void wtrans_all_kernel(const float* __restrict__ w0, const float* __restrict__ w1,
                                  const float* __restrict__ w2, const float* __restrict__ w3,
                                  const float* __restrict__ w4, const float* __restrict__ w5,
                                  const float* __restrict__ w6, const float* __restrict__ w7,
                                  const float* __restrict__ w8, float* __restrict__ wt)
{
    const float* ws[GG_NLAYERS] = {w0, w1, w2, w3, w4, w5, w6, w7, w8};
    // compute sizes/offsets
    int total = 0;
    int off[GG_NLAYERS];
    #pragma unroll
    for (int l = 0; l < GG_NLAYERS; ++l) {
        off[l] = total;
        total += c_CIN[l] * c_COUT[l] * c_NKK[l];
    }
    for (int idx = blockIdx.x * blockDim.x + threadIdx.x; idx < total;
         idx += gridDim.x * blockDim.x) {
        int layer = 0;
        #pragma unroll
        for (int l = 1; l < GG_NLAYERS; ++l)
            if (idx >= off[l]) layer = l;
        int local = idx - off[layer];
        int Cout = c_COUT[layer], Cin = c_CIN[layer], NkK = c_NKK[layer];
        int co  = local % Cout;
        int t   = local / Cout;
        int ci  = t % Cin;
        int tap = t / Cin;
        wt[idx] = ws[layer][(co * Cin + ci) * NkK + tap];
    }
}

// ---------------------------------------------------------------------------
// Lift (K=79, dilation 2^s, /2^s) fused with pool4. 4co x 4l thread tile,
// inner loop on packed fp32x2 (2 MAC/instr).  (R4 version — best measured)
// ---------------------------------------------------------------------------
__launch_bounds__(416)
__global__ void lift_pool_kernel(const float* __restrict__ x,
                                 const float* __restrict__ w,
                                 float* __restrict__ out, int s)
{
    extern __shared__ float sm[];
    float* sw = sm;             // [79][52] pre-scaled weights
    float* sx = sm + 79 * 52;   // input window
    const int d = 1 << s;
    const float invd = 1.0f / (float)d;
    const int b   = blockIdx.y;
    const int l0  = blockIdx.x * 128;
    const int tid = threadIdx.x;

    for (int t = tid; t < 79 * 52; t += 416) {
        int k = t / 52, co = t - k * 52;
        sw[t] = (co < NC1) ? w[co * NK1 + k] * invd : 0.0f;
    }
    const int nx = 128 + 78 * d + 8;
    const int gb = l0 - 39 * d;
    const float* xb = x + (size_t)b * LIN;
    for (int t = tid; t < nx; t += 416) {
        int g = gb + t;
        sx[t] = (g >= 0 && g < LIN) ? xb[g] : 0.0f;
    }
    __syncthreads();

    const int lg   = tid & 31;
    const int cg   = tid >> 5;
    const int co0  = cg * 4;
    const int base = lg * 4;
    unsigned long long acc2[4][2] = {};

    if (d >= 4) {
        #pragma unroll 4
        for (int k = 0; k < NK1; ++k) {
            ulonglong2 xq = *reinterpret_cast<const ulonglong2*>(&sx[base + k * d]);
            float4 wv = *reinterpret_cast<const float4*>(&sw[k * 52 + co0]);
            float wa[4] = {wv.x, wv.y, wv.z, wv.w};
            #pragma unroll
            for (int r = 0; r < 4; ++r) {
                unsigned long long wp = pack2(wa[r], wa[r]);
                fma2(acc2[r][0], wp, xq.x);
                fma2(acc2[r][1], wp, xq.y);
            }
        }
    } else if (d == 2) {
        float x0 = sx[base], x1 = sx[base+1], x2 = sx[base+2], x3 = sx[base+3];
        for (int k = 0; k < NK1; ++k) {
            float4 wv = *reinterpret_cast<const float4*>(&sw[k * 52 + co0]);
            float wa[4] = {wv.x, wv.y, wv.z, wv.w};
            unsigned long long xp0 = pack2(x0, x1), xp1 = pack2(x2, x3);
            #pragma unroll
            for (int r = 0; r < 4; ++r) {
                unsigned long long wp = pack2(wa[r], wa[r]);
                fma2(acc2[r][0], wp, xp0);
                fma2(acc2[r][1], wp, xp1);
            }
            x0 = x2; x1 = x3;
            x2 = sx[base + 2*k + 4];
            x3 = sx[base + 2*k + 5];
        }
    } else {
        float x0 = sx[base], x1 = sx[base+1], x2 = sx[base+2], x3 = sx[base+3];
        for (int k = 0; k < NK1; ++k) {
            float4 wv = *reinterpret_cast<const float4*>(&sw[k * 52 + co0]);
            float wa[4] = {wv.x, wv.y, wv.z, wv.w};
            unsigned long long xp0 = pack2(x0, x1), xp1 = pack2(x2, x3);
            #pragma unroll
            for (int r = 0; r < 4; ++r) {
                unsigned long long wp = pack2(wa[r], wa[r]);
                fma2(acc2[r][0], wp, xp0);
                fma2(acc2[r][1], wp, xp1);
            }
            x0 = x1; x1 = x2; x2 = x3;
            x3 = sx[base + k + 4];
        }
    }

    const int lp = blockIdx.x * 32 + lg;
    #pragma unroll
    for (int r = 0; r < 4; ++r) {
        int co = co0 + r;
        if (co < NC1) {
            float2 a = unpack2(acc2[r][0]);
            float2 c = unpack2(acc2[r][1]);
            float m = fmaxf(fmaxf(a.x, a.y), fmaxf(c.x, c.y));
            out[(((size_t)b * NC1 + co) * NSC + s) * LP1 + lp] = m;
        }
    }
}

// ---------------------------------------------------------------------------
// GConvGG, tiled GEMM over ci per (i,k). 4x4 thread tile on fp32x2.
// (R4 version; ONLY change: As fill reads pre-transposed weights, coalesced)
// fuse != 0: apply per-channel BN (g_scale/g_shift) + ReLU when loading Bs.
// ---------------------------------------------------------------------------
template <int COT, int LT>
__launch_bounds__((COT/4)*(LT/4))
__global__ void gg_kernel(const float* __restrict__ in, const float* __restrict__ wt,
                          float* __restrict__ out,
                          int Cin, int Cout, int Hin, int Nk, int L, int fuse)
{
    const int CIC = 16;
    const int TLn = LT / 4;
    const int NT  = (COT/4) * TLn;
    __shared__ __align__(16) float As[CIC][COT];
    __shared__ __align__(16) float Bs[CIC][LT];
    __shared__ float ssc[408], ssh[408];

    const int Hout = Hin - Nk + 1;
    const int s   = blockIdx.z % Hout;
    const int b   = blockIdx.z / Hout;
    const int co0 = blockIdx.y * COT;
    const int l0  = blockIdx.x * LT;
    const int tid = threadIdx.x;
    const int tco = (tid / TLn) * 4;
    const int tl  = (tid % TLn) * 4;

    if (fuse) {
        for (int t = tid; t < Cin; t += NT) {
            ssc[t] = g_scale[t];
            ssh[t] = g_shift[t];
        }
    }

    unsigned long long acc2[4][2] = {};

    for (int i = 0; i < Nk; ++i) {
        const int dd = 1 << (s + i);
        const float invd = 1.0f / (float)dd;
        const float* inb = in + (((size_t)b * Cin) * Hin + (s + i)) * L;
        for (int k = 0; k < 3; ++k) {
            const int off = (k - 1) * dd;
            const float* wtap = wt + (size_t)(i * 3 + k) * Cin * Cout;
            for (int cc = 0; cc < Cin; cc += CIC) {
                __syncthreads();
                for (int t = tid; t < CIC * COT; t += NT) {
                    int row = t / COT, col = t - row * COT;
                    int ci = cc + row, co = co0 + col;
                    float v = 0.0f;
                    if (ci < Cin && co < Cout)
                        v = wtap[ci * Cout + co] * invd;   // coalesced in co
                    As[row][col] = v;
                }
                for (int t = tid; t < CIC * LT; t += NT) {
                    int row = t / LT, col = t - row * LT;
                    int ci = cc + row;
                    int l  = l0 + off + col;
                    float v = 0.0f;
                    if (ci < Cin && l >= 0 && l < L) {
                        v = inb[(size_t)ci * Hin * L + l];
                        if (fuse) v = fmaxf(fmaf(v, ssc[ci], ssh[ci]), 0.0f);
                    }
                    Bs[row][col] = v;
                }
                __syncthreads();
                #pragma unroll
                for (int ci = 0; ci < CIC; ++ci) {
                    float4 av = *reinterpret_cast<const float4*>(&As[ci][tco]);
                    ulonglong2 bq = *reinterpret_cast<const ulonglong2*>(&Bs[ci][tl]);
                    float a4[4] = {av.x, av.y, av.z, av.w};
                    #pragma unroll
                    for (int r = 0; r < 4; ++r) {
                        unsigned long long ap = pack2(a4[r], a4[r]);
                        fma2(acc2[r][0], ap, bq.x);
                        fma2(acc2[r][1], ap, bq.y);
                    }
                }
            }
        }
    }

    #pragma unroll
    for (int r = 0; r < 4; ++r) {
        int co = co0 + tco + r;
        if (co < Cout) {
            size_t ob = (((size_t)b * Cout + co) * Hout + s) * L + l0 + tl;
            float2 lo = unpack2(acc2[r][0]);
            float2 hi = unpack2(acc2[r][1]);
            float4 v = make_float4(lo.x, lo.y, hi.x, hi.y);
            *reinterpret_cast<float4*>(&out[ob]) = v;
        }
    }
}

// ---------------------------------------------------------------------------
// BN stats: per-channel per-split partial sums (no atomics, no zeroing).
// grid = (C, S), block = 256
// ---------------------------------------------------------------------------
__global__ void stats_kernel(const float* __restrict__ in, int C, int HL)
{
    const int c  = blockIdx.x;
    const int sp = blockIdx.y, S = gridDim.y;
    float s = 0.0f, s2 = 0.0f;
    for (int b = 0; b < NB; ++b) {
        const float* p = in + ((size_t)b * C + c) * HL;
        for (int r = sp * blockDim.x + threadIdx.x; r < HL; r += S * blockDim.x) {
            float v = p[r];
            s += v; s2 = fmaf(v, v, s2);
        }
    }
    __shared__ float rs[256], rq[256];
    rs[threadIdx.x] = s; rq[threadIdx.x] = s2;
    __syncthreads();
    for (int st = 128; st > 0; st >>= 1) {
        if (threadIdx.x < st) {
            rs[threadIdx.x] += rs[threadIdx.x + st];
            rq[threadIdx.x] += rq[threadIdx.x + st];
        }
        __syncthreads();
    }
    if (threadIdx.x == 0) {
        g_psum[c * SMAX + sp] = rs[0];
        g_psqs[c * SMAX + sp] = rq[0];
    }
}

// reduce partials -> per-channel scale/shift
__global__ void finalize_kernel(const float* __restrict__ gamma,
                                const float* __restrict__ beta,
                                int C, int S, double invN)
{
    int c = blockIdx.x * blockDim.x + threadIdx.x;
    if (c >= C) return;
    double s = 0.0, q = 0.0;
    for (int i = 0; i < S; ++i) {
        s += (double)g_psum[c * SMAX + i];
        q += (double)g_psqs[c * SMAX + i];
    }
    double m   = s * invN;
    double var = q * invN - m * m;
    float inv = rsqrtf((float)var + 2e-5f);
    float sc  = gamma[c] * inv;
    g_scale[c] = sc;
    g_shift[c] = beta[c] - (float)m * sc;
}

// ---------------------------------------------------------------------------
// BN apply + ReLU + pool4 (pooled stages only; scale/shift precomputed)
// ---------------------------------------------------------------------------
__global__ void bn_pool_kernel(const float* __restrict__ in, float* __restrict__ out,
                               int C, int H, int Lin)
{
    __shared__ float ssc[408], ssh[408];
    for (int c = threadIdx.x; c < C; c += blockDim.x) {
        ssc[c] = g_scale[c];
        ssh[c] = g_shift[c];
    }
    __syncthreads();

    const int Lout = Lin / 4;
    const size_t n = (size_t)NB * C * H * Lout;
    for (size_t i = (size_t)blockIdx.x * blockDim.x + threadIdx.x; i < n;
         i += (size_t)gridDim.x * blockDim.x) {
        int lp = (int)(i % Lout);
        size_t t = i / Lout;
        int h = (int)(t % H); t /= H;           // t = b*C + c
        int c = (int)(t % C);
        size_t ibase = (t * (size_t)H + h) * (size_t)Lin;
        float sc = ssc[c], sh = ssh[c];
        const float* p = in + ibase + 4 * (size_t)lp;
        float y0 = fmaf(p[0], sc, sh);
        float y1 = fmaf(p[1], sc, sh);
        float y2 = fmaf(p[2], sc, sh);
        float y3 = fmaf(p[3], sc, sh);
        float y = fmaxf(fmaxf(y0, y1), fmaxf(y2, y3));
        out[i] = fmaxf(y, 0.0f);
    }
}

// ---------------------------------------------------------------------------
// Final: fused bn10+relu, mean over L=32, 1x1 classifier -> out [8,10]
// ---------------------------------------------------------------------------
__global__ void final_kernel(const float* __restrict__ in,   // raw [8][408][32]
                             const float* __restrict__ w11,
                             float* __restrict__ out)
{
    __shared__ float mean[NB * 408];
    for (int i = threadIdx.x; i < NB * 408; i += blockDim.x) {
        int c = i % 408;
        float sc = g_scale[c], sh = g_shift[c];
        const float* p = in + (size_t)i * 32;
        float s = 0.0f;
        #pragma unroll
        for (int j = 0; j < 32; ++j)
            s += fmaxf(fmaf(p[j], sc, sh), 0.0f);
        mean[i] = s * (1.0f / 32.0f);
    }
    __syncthreads();
    for (int i = threadIdx.x; i < NB * 10; i += blockDim.x) {
        int b = i / 10, cls = i - b * 10;
        const float* mb = &mean[b * 408];
        const float* wr = &w11[cls * 408];
        float s = 0.0f;
        for (int ci = 0; ci < 408; ++ci) s = fmaf(mb[ci], wr[ci], s);
        out[i] = s;
    }
}

// ---------------------------------------------------------------------------
// Host side
// ---------------------------------------------------------------------------
static void bn_stats(const float* in, const float* g, const float* bta, int C, int H, int Lin)
{
    int HL = H * Lin;
    int S = (NB * HL) / (256 * 16);
    if (S < 1) S = 1; if (S > SMAX) S = SMAX;
    stats_kernel<<<dim3(C, S), 256>>>(in, C, HL);
    double invN = 1.0 / ((double)NB * HL);
    finalize_kernel<<<(C + 255) / 256, 256>>>(g, bta, C, S, invN);
}

static void bn_pool(const float* in, float* out, int C, int H, int Lin)
{
    size_t n = (size_t)NB * C * H * (Lin / 4);
    int grid = (int)((n + 255) / 256);
    if (grid > 8192) grid = 8192;
    bn_pool_kernel<<<grid, 256>>>(in, out, C, H, Lin);
}

static void gg(const float* in, const float* wt, float* out,
               int Cin, int Cout, int Hin, int Nk, int L, int fuse)
{
    int Hout = Hin - Nk + 1;
    if (L >= 64)
        gg_kernel<64, 64><<<dim3(L / 64, (Cout + 63) / 64, NB * Hout), 256>>>(
            in, wt, out, Cin, Cout, Hin, Nk, L, fuse);
    else
        gg_kernel<64, 32><<<dim3(L / 32, (Cout + 63) / 64, NB * Hout), 128>>>(
            in, wt, out, Cin, Cout, Hin, Nk, L, fuse);
}

extern "C" void kernel_launch(void* const* d_in, const int* in_sizes, int n_in,
                              void* d_out, int out_size)
{
    const float* x   = (const float*)d_in[0];
    const float* w1  = (const float*)d_in[1];
    const float* wsrc[9];
    for (int i = 0; i < 9; ++i) wsrc[i] = (const float*)d_in[2 + i];   // w2..w10
    const float* w11 = (const float*)d_in[11];
    const float* gb[20];
    for (int i = 0; i < 20; ++i) gb[i] = (const float*)d_in[12 + i];

    float *A, *B, *WT;
    cudaGetSymbolAddress((void**)&A, g_bufA);
    cudaGetSymbolAddress((void**)&B, g_bufB);
    cudaGetSymbolAddress((void**)&WT, g_wT);

    cudaFuncSetAttribute(lift_pool_kernel,
                         cudaFuncAttributeMaxDynamicSharedMemorySize, 98304);

    // layer dims: {Cin, Cout, Nk} — must match c_CIN/c_COUT/c_NKK order
    const int ldims[9][3] = {
        {51, 51, 3}, {51, 51, 1}, {51, 102, 3}, {102, 102, 1},
        {102, 204, 3}, {204, 204, 1}, {204, 204, 1}, {204, 408, 3}, {408, 408, 1}
    };
    size_t wofs[10];
    wofs[0] = 0;
    for (int i = 0; i < 9; ++i)
        wofs[i + 1] = wofs[i] + (size_t)ldims[i][0] * ldims[i][1] * ldims[i][2] * 3;

    // single transpose pass for all gg weights
    wtrans_all_kernel<<<1024, 256>>>(wsrc[0], wsrc[1], wsrc[2], wsrc[3], wsrc[4],
                                     wsrc[5], wsrc[6], wsrc[7], wsrc[8], WT);

    // lift + pool4 -> A [8,51,9,8192]
    for (int s = 0; s < NSC; ++s) {
        int d = 1 << s;
        size_t smem = (size_t)(79 * 52 + 128 + 78 * d + 8) * sizeof(float);
        lift_pool_kernel<<<dim3(LIN / 128, NB), 416, smem>>>(x, w1, A, s);
    }

    bn_stats(A, gb[0], gb[1], 51, 9, 8192);
    bn_pool(A, B, 51, 9, 8192);                       // -> B [8,51,9,2048]
    gg(B, WT + wofs[0], A, 51, 51, 9, 3, 2048, 0);    // -> A [8,51,7,2048]
    bn_stats(A, gb[2], gb[3], 51, 7, 2048);
    gg(A, WT + wofs[1], B, 51, 51, 7, 1, 2048, 1);    // -> B [8,51,7,2048]
    bn_stats(B, gb[4], gb[5], 51, 7, 2048);
    bn_pool(B, A, 51, 7, 2048);                       // -> A [8,51,7,512]
    gg(A, WT + wofs[2], B, 51, 102, 7, 3, 512, 0);    // -> B [8,102,5,512]
    bn_stats(B, gb[6], gb[7], 102, 5, 512);
    gg(B, WT + wofs[3], A, 102, 102, 5, 1, 512, 1);   // -> A [8,102,5,512]
    bn_stats(A, gb[8], gb[9], 102, 5, 512);
    bn_pool(A, B, 102, 5, 512);                       // -> B [8,102,5,128]
    gg(B, WT + wofs[4], A, 102, 204, 5, 3, 128, 0);   // -> A [8,204,3,128]
    bn_stats(A, gb[10], gb[11], 204, 3, 128);
    gg(A, WT + wofs[5], B, 204, 204, 3, 1, 128, 1);   // -> B [8,204,3,128]
    bn_stats(B, gb[12], gb[13], 204, 3, 128);
    gg(B, WT + wofs[6], A, 204, 204, 3, 1, 128, 1);   // -> A [8,204,3,128]
    bn_stats(A, gb[14], gb[15], 204, 3, 128);
    bn_pool(A, B, 204, 3, 128);                       // -> B [8,204,3,32]
    gg(B, WT + wofs[7], A, 204, 408, 3, 3, 32, 0);    // -> A [8,408,1,32]
    bn_stats(A, gb[16], gb[17], 408, 1, 32);
    gg(A, WT + wofs[8], B, 408, 408, 1, 1, 32, 1);    // -> B [8,408,1,32]
    bn_stats(B, gb[18], gb[19], 408, 1, 32);

    final_kernel<<<1, 512>>>(B, w11, (float*)d_out);
}

// round 10
// speedup vs baseline: 1.4950x; 1.2150x over previous
#include <cuda_runtime.h>

#define NB   8
#define LIN  32768
#define NC1  51
#define NK1  79
#define NSC  9
#define LP1  8192
#define SMAX 64

// scratch (allocation-free rule: device globals)
__device__ float g_bufA[30081024];   // max 8*51*9*8192
__device__ float g_bufB[7520256];    // max 8*51*9*2048
__device__ float g_wT[1800000];      // transposed gg weights [layer][tap][ci][co]
__device__ float g_psum[408 * SMAX];
__device__ float g_psqs[408 * SMAX];
__device__ float g_scale[408];
__device__ float g_shift[408];

// layer dims for the 9 gg layers: {Cin, Cout, Nk*3}
#define GG_NLAYERS 9
__device__ __constant__ int c_CIN[GG_NLAYERS]  = {51, 51, 51, 102, 102, 204, 204, 204, 408};
__device__ __constant__ int c_COUT[GG_NLAYERS] = {51, 51, 102, 102, 204, 204, 204, 408, 408};
__device__ __constant__ int c_NKK[GG_NLAYERS]  = {9, 3, 9, 3, 9, 3, 3, 9, 3};

// ---------------------------------------------------------------------------
// packed fp32x2 helpers (FFMA2 — only reachable via PTX)
// ---------------------------------------------------------------------------
__device__ __forceinline__ unsigned long long pack2(float lo, float hi) {
    unsigned long long r;
    asm("mov.b64 %0, {%1, %2};" : "=l"(r) : "f"(lo), "f"(hi));
    return r;
}
__device__ __forceinline__ void fma2(unsigned long long& d,
                                     unsigned long long a, unsigned long long b) {
    asm("fma.rn.f32x2 %0, %1, %2, %0;" : "+l"(d) : "l"(a), "l"(b));
}
__device__ __forceinline__ float2 unpack2(unsigned long long v) {
    float2 f;
    asm("mov.b64 {%0, %1}, %2;" : "=f"(f.x), "=f"(f.y) : "l"(v));
    return f;
}

// ---------------------------------------------------------------------------
// One-shot weight transpose for ALL gg layers:
// w[Cout][Cin][NkK] -> wt[tap][ci][co] per layer, concatenated.
// ---------------------------------------------------------------------------
__global__ void wtrans_all_kernel(const float* __restrict__ w0, const float* __restrict__ w1,
                                  const float* __restrict__ w2, const float* __restrict__ w3,
                                  const float* __restrict__ w4, const float* __restrict__ w5,
                                  const float* __restrict__ w6, const float* __restrict__ w7,
                                  const float* __restrict__ w8, float* __restrict__ wt)
{
    const float* ws[GG_NLAYERS] = {w0, w1, w2, w3, w4, w5, w6, w7, w8};
    int total = 0;
    int off[GG_NLAYERS];
    #pragma unroll
    for (int l = 0; l < GG_NLAYERS; ++l) {
        off[l] = total;
        total += c_CIN[l] * c_COUT[l] * c_NKK[l];
    }
    for (int idx = blockIdx.x * blockDim.x + threadIdx.x; idx < total;
         idx += gridDim.x * blockDim.x) {
        int layer = 0;
        #pragma unroll
        for (int l = 1; l < GG_NLAYERS; ++l)
            if (idx >= off[l]) layer = l;
        int local = idx - off[layer];
        int Cout = c_COUT[layer], Cin = c_CIN[layer], NkK = c_NKK[layer];
        int co  = local % Cout;
        int t   = local / Cout;
        int ci  = t % Cin;
        int tap = t / Cin;
        wt[idx] = ws[layer][(co * Cin + ci) * NkK + tap];
    }
}

// ---------------------------------------------------------------------------
// Lift (K=79, dilation 2^s, /2^s) fused with pool4, ALL scales in one launch
// (s = blockIdx.z). 4co x 4l thread tile on packed fp32x2.
// ---------------------------------------------------------------------------
__launch_bounds__(416)
__global__ void lift_pool_kernel(const float* __restrict__ x,
                                 const float* __restrict__ w,
                                 float* __restrict__ out)
{
    extern __shared__ float sm[];
    float* sw = sm;             // [79][52] pre-scaled weights
    float* sx = sm + 79 * 52;   // input window
    const int s = blockIdx.z;
    const int d = 1 << s;
    const float invd = 1.0f / (float)d;
    const int b   = blockIdx.y;
    const int l0  = blockIdx.x * 128;
    const int tid = threadIdx.x;

    for (int t = tid; t < 79 * 52; t += 416) {
        int k = t / 52, co = t - k * 52;
        sw[t] = (co < NC1) ? w[co * NK1 + k] * invd : 0.0f;
    }
    const int nx = 128 + 78 * d + 8;
    const int gb = l0 - 39 * d;
    const float* xb = x + (size_t)b * LIN;
    for (int t = tid; t < nx; t += 416) {
        int g = gb + t;
        sx[t] = (g >= 0 && g < LIN) ? xb[g] : 0.0f;
    }
    __syncthreads();

    const int lg   = tid & 31;
    const int cg   = tid >> 5;
    const int co0  = cg * 4;
    const int base = lg * 4;
    unsigned long long acc2[4][2] = {};

    if (d >= 4) {
        #pragma unroll 4
        for (int k = 0; k < NK1; ++k) {
            ulonglong2 xq = *reinterpret_cast<const ulonglong2*>(&sx[base + k * d]);
            float4 wv = *reinterpret_cast<const float4*>(&sw[k * 52 + co0]);
            float wa[4] = {wv.x, wv.y, wv.z, wv.w};
            #pragma unroll
            for (int r = 0; r < 4; ++r) {
                unsigned long long wp = pack2(wa[r], wa[r]);
                fma2(acc2[r][0], wp, xq.x);
                fma2(acc2[r][1], wp, xq.y);
            }
        }
    } else if (d == 2) {
        float x0 = sx[base], x1 = sx[base+1], x2 = sx[base+2], x3 = sx[base+3];
        for (int k = 0; k < NK1; ++k) {
            float4 wv = *reinterpret_cast<const float4*>(&sw[k * 52 + co0]);
            float wa[4] = {wv.x, wv.y, wv.z, wv.w};
            unsigned long long xp0 = pack2(x0, x1), xp1 = pack2(x2, x3);
            #pragma unroll
            for (int r = 0; r < 4; ++r) {
                unsigned long long wp = pack2(wa[r], wa[r]);
                fma2(acc2[r][0], wp, xp0);
                fma2(acc2[r][1], wp, xp1);
            }
            x0 = x2; x1 = x3;
            x2 = sx[base + 2*k + 4];
            x3 = sx[base + 2*k + 5];
        }
    } else {
        float x0 = sx[base], x1 = sx[base+1], x2 = sx[base+2], x3 = sx[base+3];
        for (int k = 0; k < NK1; ++k) {
            float4 wv = *reinterpret_cast<const float4*>(&sw[k * 52 + co0]);
            float wa[4] = {wv.x, wv.y, wv.z, wv.w};
            unsigned long long xp0 = pack2(x0, x1), xp1 = pack2(x2, x3);
            #pragma unroll
            for (int r = 0; r < 4; ++r) {
                unsigned long long wp = pack2(wa[r], wa[r]);
                fma2(acc2[r][0], wp, xp0);
                fma2(acc2[r][1], wp, xp1);
            }
            x0 = x1; x1 = x2; x2 = x3;
            x3 = sx[base + k + 4];
        }
    }

    const int lp = blockIdx.x * 32 + lg;
    #pragma unroll
    for (int r = 0; r < 4; ++r) {
        int co = co0 + r;
        if (co < NC1) {
            float2 a = unpack2(acc2[r][0]);
            float2 c = unpack2(acc2[r][1]);
            float m = fmaxf(fmaxf(a.x, a.y), fmaxf(c.x, c.y));
            out[(((size_t)b * NC1 + co) * NSC + s) * LP1 + lp] = m;
        }
    }
}

// ---------------------------------------------------------------------------
// GConvGG: tiled GEMM over ci per (i,k) tap, coalesced transposed weights,
// ping-pong double-buffered fills (ONE __syncthreads per phase; global loads
// for phase p+1 overlap compute of phase p). 4x4 thread tile on fp32x2.
// fuse != 0: per-channel BN + ReLU applied when loading the input tile.
// ---------------------------------------------------------------------------
template <int COT, int LT>
__launch_bounds__((COT/4)*(LT/4))
__global__ void gg_kernel(const float* __restrict__ in, const float* __restrict__ wt,
                          float* __restrict__ out,
                          int Cin, int Cout, int Hin, int Nk, int L, int fuse)
{
    const int CIC = 16;
    const int TLn = LT / 4;
    const int NT  = (COT/4) * TLn;
    const int AE  = (CIC * COT) / NT;
    const int BE  = (CIC * LT) / NT;
    __shared__ __align__(16) float As[2][CIC][COT];
    __shared__ __align__(16) float Bs[2][CIC][LT];
    __shared__ float ssc[408], ssh[408];

    const int Hout = Hin - Nk + 1;
    const int s   = blockIdx.z % Hout;
    const int b   = blockIdx.z / Hout;
    const int co0 = blockIdx.y * COT;
    const int l0  = blockIdx.x * LT;
    const int tid = threadIdx.x;
    const int tco = (tid / TLn) * 4;
    const int tl  = (tid % TLn) * 4;

    if (fuse) {
        for (int t = tid; t < Cin; t += NT) {
            ssc[t] = g_scale[t];
            ssh[t] = g_shift[t];
        }
    }
    __syncthreads();   // ssc/ssh visible before any load_phase

    const int nCh = (Cin + CIC - 1) / CIC;
    const int P   = Nk * 3 * nCh;

    float aReg[AE], bReg[BE];

    auto load_phase = [&](int p) {
        int tap = p / nCh, ch = p - tap * nCh;
        int i = tap / 3, k = tap - i * 3;
        int dd = 1 << (s + i);
        float invd = 1.0f / (float)dd;
        int off = (k - 1) * dd;
        int cc = ch * CIC;
        const float* wtap = wt + (size_t)tap * Cin * Cout;
        const float* inb  = in + (((size_t)b * Cin) * Hin + (s + i)) * L;
        #pragma unroll
        for (int j = 0; j < AE; ++j) {
            int t = tid + j * NT;
            int row = t / COT, col = t - row * COT;
            int ci = cc + row, co = co0 + col;
            float v = 0.0f;
            if (ci < Cin && co < Cout)
                v = wtap[ci * Cout + co] * invd;
            aReg[j] = v;
        }
        #pragma unroll
        for (int j = 0; j < BE; ++j) {
            int t = tid + j * NT;
            int row = t / LT, col = t - row * LT;
            int ci = cc + row;
            int l  = l0 + off + col;
            float v = 0.0f;
            if (ci < Cin && l >= 0 && l < L) {
                v = inb[(size_t)ci * Hin * L + l];
                if (fuse) v = fmaxf(fmaf(v, ssc[ci], ssh[ci]), 0.0f);
            }
            bReg[j] = v;
        }
    };

    load_phase(0);
    unsigned long long acc2[4][2] = {};

    for (int p = 0; p < P; ++p) {
        const int bufi = p & 1;
        #pragma unroll
        for (int j = 0; j < AE; ++j) {
            int t = tid + j * NT;
            As[bufi][t / COT][t % COT] = aReg[j];
        }
        #pragma unroll
        for (int j = 0; j < BE; ++j) {
            int t = tid + j * NT;
            Bs[bufi][t / LT][t % LT] = bReg[j];
        }
        __syncthreads();
        if (p + 1 < P) load_phase(p + 1);   // LDGs overlap compute below
        #pragma unroll
        for (int ci = 0; ci < CIC; ++ci) {
            float4 av = *reinterpret_cast<const float4*>(&As[bufi][ci][tco]);
            ulonglong2 bq = *reinterpret_cast<const ulonglong2*>(&Bs[bufi][ci][tl]);
            float a4[4] = {av.x, av.y, av.z, av.w};
            #pragma unroll
            for (int r = 0; r < 4; ++r) {
                unsigned long long ap = pack2(a4[r], a4[r]);
                fma2(acc2[r][0], ap, bq.x);
                fma2(acc2[r][1], ap, bq.y);
            }
        }
    }

    #pragma unroll
    for (int r = 0; r < 4; ++r) {
        int co = co0 + tco + r;
        if (co < Cout) {
            size_t ob = (((size_t)b * Cout + co) * Hout + s) * L + l0 + tl;
            float2 lo = unpack2(acc2[r][0]);
            float2 hi = unpack2(acc2[r][1]);
            float4 v = make_float4(lo.x, lo.y, hi.x, hi.y);
            *reinterpret_cast<float4*>(&out[ob]) = v;
        }
    }
}

// ---------------------------------------------------------------------------
// BN stats: per-channel per-split partial sums (no atomics, no zeroing).
// grid = (C, S), block = 256
// ---------------------------------------------------------------------------
__global__ void stats_kernel(const float* __restrict__ in, int C, int HL)
{
    const int c  = blockIdx.x;
    const int sp = blockIdx.y, S = gridDim.y;
    float s = 0.0f, s2 = 0.0f;
    for (int b = 0; b < NB; ++b) {
        const float* p = in + ((size_t)b * C + c) * HL;
        for (int r = sp * blockDim.x + threadIdx.x; r < HL; r += S * blockDim.x) {
            float v = p[r];
            s += v; s2 = fmaf(v, v, s2);
        }
    }
    __shared__ float rs[256], rq[256];
    rs[threadIdx.x] = s; rq[threadIdx.x] = s2;
    __syncthreads();
    for (int st = 128; st > 0; st >>= 1) {
        if (threadIdx.x < st) {
            rs[threadIdx.x] += rs[threadIdx.x + st];
            rq[threadIdx.x] += rq[threadIdx.x + st];
        }
        __syncthreads();
    }
    if (threadIdx.x == 0) {
        g_psum[c * SMAX + sp] = rs[0];
        g_psqs[c * SMAX + sp] = rq[0];
    }
}

// reduce partials -> per-channel scale/shift
__global__ void finalize_kernel(const float* __restrict__ gamma,
                                const float* __restrict__ beta,
                                int C, int S, double invN)
{
    int c = blockIdx.x * blockDim.x + threadIdx.x;
    if (c >= C) return;
    double s = 0.0, q = 0.0;
    for (int i = 0; i < S; ++i) {
        s += (double)g_psum[c * SMAX + i];
        q += (double)g_psqs[c * SMAX + i];
    }
    double m   = s * invN;
    double var = q * invN - m * m;
    float inv = rsqrtf((float)var + 2e-5f);
    float sc  = gamma[c] * inv;
    g_scale[c] = sc;
    g_shift[c] = beta[c] - (float)m * sc;
}

// ---------------------------------------------------------------------------
// BN apply + ReLU + pool4 (pooled stages only; scale/shift precomputed)
// ---------------------------------------------------------------------------
__global__ void bn_pool_kernel(const float* __restrict__ in, float* __restrict__ out,
                               int C, int H, int Lin)
{
    __shared__ float ssc[408], ssh[408];
    for (int c = threadIdx.x; c < C; c += blockDim.x) {
        ssc[c] = g_scale[c];
        ssh[c] = g_shift[c];
    }
    __syncthreads();

    const int Lout = Lin / 4;
    const size_t n = (size_t)NB * C * H * Lout;
    for (size_t i = (size_t)blockIdx.x * blockDim.x + threadIdx.x; i < n;
         i += (size_t)gridDim.x * blockDim.x) {
        int lp = (int)(i % Lout);
        size_t t = i / Lout;
        int h = (int)(t % H); t /= H;           // t = b*C + c
        int c = (int)(t % C);
        size_t ibase = (t * (size_t)H + h) * (size_t)Lin;
        float sc = ssc[c], sh = ssh[c];
        const float* p = in + ibase + 4 * (size_t)lp;
        float y0 = fmaf(p[0], sc, sh);
        float y1 = fmaf(p[1], sc, sh);
        float y2 = fmaf(p[2], sc, sh);
        float y3 = fmaf(p[3], sc, sh);
        float y = fmaxf(fmaxf(y0, y1), fmaxf(y2, y3));
        out[i] = fmaxf(y, 0.0f);
    }
}

// ---------------------------------------------------------------------------
// Final: fused bn10+relu, mean over L=32, 1x1 classifier -> out [8,10]
// ---------------------------------------------------------------------------
__global__ void final_kernel(const float* __restrict__ in,   // raw [8][408][32]
                             const float* __restrict__ w11,
                             float* __restrict__ out)
{
    __shared__ float mean[NB * 408];
    for (int i = threadIdx.x; i < NB * 408; i += blockDim.x) {
        int c = i % 408;
        float sc = g_scale[c], sh = g_shift[c];
        const float* p = in + (size_t)i * 32;
        float s = 0.0f;
        #pragma unroll
        for (int j = 0; j < 32; ++j)
            s += fmaxf(fmaf(p[j], sc, sh), 0.0f);
        mean[i] = s * (1.0f / 32.0f);
    }
    __syncthreads();
    for (int i = threadIdx.x; i < NB * 10; i += blockDim.x) {
        int b = i / 10, cls = i - b * 10;
        const float* mb = &mean[b * 408];
        const float* wr = &w11[cls * 408];
        float s = 0.0f;
        for (int ci = 0; ci < 408; ++ci) s = fmaf(mb[ci], wr[ci], s);
        out[i] = s;
    }
}

// ---------------------------------------------------------------------------
// Host side
// ---------------------------------------------------------------------------
static void bn_stats(const float* in, const float* g, const float* bta, int C, int H, int Lin)
{
    int HL = H * Lin;
    int S = (NB * HL) / (256 * 16);
    if (S < 1) S = 1; if (S > SMAX) S = SMAX;
    stats_kernel<<<dim3(C, S), 256>>>(in, C, HL);
    double invN = 1.0 / ((double)NB * HL);
    finalize_kernel<<<(C + 255) / 256, 256>>>(g, bta, C, S, invN);
}

static void bn_pool(const float* in, float* out, int C, int H, int Lin)
{
    size_t n = (size_t)NB * C * H * (Lin / 4);
    int grid = (int)((n + 255) / 256);
    if (grid > 8192) grid = 8192;
    bn_pool_kernel<<<grid, 256>>>(in, out, C, H, Lin);
}

static void gg(const float* in, const float* wt, float* out,
               int Cin, int Cout, int Hin, int Nk, int L, int fuse)
{
    int Hout = Hin - Nk + 1;
    if (L >= 64)
        gg_kernel<64, 64><<<dim3(L / 64, (Cout + 63) / 64, NB * Hout), 256>>>(
            in, wt, out, Cin, Cout, Hin, Nk, L, fuse);
    else
        gg_kernel<64, 32><<<dim3(L / 32, (Cout + 63) / 64, NB * Hout), 128>>>(
            in, wt, out, Cin, Cout, Hin, Nk, L, fuse);
}

extern "C" void kernel_launch(void* const* d_in, const int* in_sizes, int n_in,
                              void* d_out, int out_size)
{
    const float* x   = (const float*)d_in[0];
    const float* w1  = (const float*)d_in[1];
    const float* wsrc[9];
    for (int i = 0; i < 9; ++i) wsrc[i] = (const float*)d_in[2 + i];   // w2..w10
    const float* w11 = (const float*)d_in[11];
    const float* gb[20];
    for (int i = 0; i < 20; ++i) gb[i] = (const float*)d_in[12 + i];

    float *A, *B, *WT;
    cudaGetSymbolAddress((void**)&A, g_bufA);
    cudaGetSymbolAddress((void**)&B, g_bufB);
    cudaGetSymbolAddress((void**)&WT, g_wT);

    cudaFuncSetAttribute(lift_pool_kernel,
                         cudaFuncAttributeMaxDynamicSharedMemorySize, 98304);

    // layer dims: {Cin, Cout, Nk} — must match c_CIN/c_COUT/c_NKK order
    const int ldims[9][3] = {
        {51, 51, 3}, {51, 51, 1}, {51, 102, 3}, {102, 102, 1},
        {102, 204, 3}, {204, 204, 1}, {204, 204, 1}, {204, 408, 3}, {408, 408, 1}
    };
    size_t wofs[10];
    wofs[0] = 0;
    for (int i = 0; i < 9; ++i)
        wofs[i + 1] = wofs[i] + (size_t)ldims[i][0] * ldims[i][1] * ldims[i][2] * 3;

    // launch #1: single transpose pass for all gg weights
    wtrans_all_kernel<<<1024, 256>>>(wsrc[0], wsrc[1], wsrc[2], wsrc[3], wsrc[4],
                                     wsrc[5], wsrc[6], wsrc[7], wsrc[8], WT);

    // launch #2: lift + pool4, all 9 scales in one launch -> A [8,51,9,8192]
    {
        size_t smem = (size_t)(79 * 52 + 128 + 78 * 256 + 8) * sizeof(float);
        lift_pool_kernel<<<dim3(LIN / 128, NB, NSC), 416, smem>>>(x, w1, A);
    }

    bn_stats(A, gb[0], gb[1], 51, 9, 8192);           // launches #3, #4
    bn_pool(A, B, 51, 9, 8192);                       // launch  #5 -> B [8,51,9,2048]
    gg(B, WT + wofs[0], A, 51, 51, 9, 3, 2048, 0);    // launch  #6 (profiled) -> A [8,51,7,2048]
    bn_stats(A, gb[2], gb[3], 51, 7, 2048);
    gg(A, WT + wofs[1], B, 51, 51, 7, 1, 2048, 1);    // -> B [8,51,7,2048]
    bn_stats(B, gb[4], gb[5], 51, 7, 2048);
    bn_pool(B, A, 51, 7, 2048);                       // -> A [8,51,7,512]
    gg(A, WT + wofs[2], B, 51, 102, 7, 3, 512, 0);    // -> B [8,102,5,512]
    bn_stats(B, gb[6], gb[7], 102, 5, 512);
    gg(B, WT + wofs[3], A, 102, 102, 5, 1, 512, 1);   // -> A [8,102,5,512]
    bn_stats(A, gb[8], gb[9], 102, 5, 512);
    bn_pool(A, B, 102, 5, 512);                       // -> B [8,102,5,128]
    gg(B, WT + wofs[4], A, 102, 204, 5, 3, 128, 0);   // -> A [8,204,3,128]
    bn_stats(A, gb[10], gb[11], 204, 3, 128);
    gg(A, WT + wofs[5], B, 204, 204, 3, 1, 128, 1);   // -> B [8,204,3,128]
    bn_stats(B, gb[12], gb[13], 204, 3, 128);
    gg(B, WT + wofs[6], A, 204, 204, 3, 1, 128, 1);   // -> A [8,204,3,128]
    bn_stats(A, gb[14], gb[15], 204, 3, 128);
    bn_pool(A, B, 204, 3, 128);                       // -> B [8,204,3,32]
    gg(B, WT + wofs[7], A, 204, 408, 3, 3, 32, 0);    // -> A [8,408,1,32]
    bn_stats(A, gb[16], gb[17], 408, 1, 32);
    gg(A, WT + wofs[8], B, 408, 408, 1, 1, 32, 1);    // -> B [8,408,1,32]
    bn_stats(B, gb[18], gb[19], 408, 1, 32);

    final_kernel<<<1, 512>>>(B, w11, (float*)d_out);
}